// round 12
// baseline (speedup 1.0000x reference)
#include <cuda_runtime.h>

typedef unsigned long long u64;

#define NT 640
#define BT 60
#define HD 62      /* u64 row stride, hdup */
#define RSTR 60    /* float row stride, natural (multiple of 4) */
#define B_TOT 8192
#define T_STEPS 30
#define WARM 24
#define WCH 8192   /* floats per staging chunk (32KB) */

__device__ __forceinline__ u64 pack2(float lo, float hi){
    u64 r; asm("mov.b64 %0, {%1, %2};" : "=l"(r) : "f"(lo), "f"(hi)); return r;
}
__device__ __forceinline__ void unpack2(u64 v, float& lo, float& hi){
    asm("mov.b64 {%0, %1}, %2;" : "=f"(lo), "=f"(hi) : "l"(v));
}
__device__ __forceinline__ u64 fma2(u64 a, u64 b, u64 c){
    u64 d; asm("fma.rn.f32x2 %0, %1, %2, %3;" : "=l"(d) : "l"(a), "l"(b), "l"(c)); return d;
}
__device__ __forceinline__ float sig_(float x){ return __fdividef(1.f, 1.f + __expf(-x)); }
__device__ __forceinline__ float tanh_(float x){ return 1.f - 2.f * __fdividef(1.f, __expf(2.f * x) + 1.f); }

#define CPA16(dst_u32, src) asm volatile("cp.async.cg.shared.global [%0], [%1], 16;" :: "r"(dst_u32), "l"(src))
#define CPA_COMMIT() asm volatile("cp.async.commit_group;")
#define CPA_WAIT()   asm volatile("cp.async.wait_group 0;")

__device__ __forceinline__ void stage(float* dst, const float* __restrict__ src, int nfloats, int tid){
    unsigned d = (unsigned)__cvta_generic_to_shared(dst);
    for (int i = tid; i < (nfloats >> 2); i += NT)
        CPA16(d + i * 16, src + i * 4);
    CPA_COMMIT();
}

// smem: hdup u64[136][62] | floats: hnat 128*60, m1b 128*60, wsm 2*8192, cbz 512, cb1/cb2/cwo 384, red 240, predb 60
#define SMEM_BYTES (136*HD*8 + (128*RSTR + 128*RSTR + 2*WCH + 512 + 384 + 240 + 60) * 4)

__global__ void __launch_bounds__(NT, 1)
fused_lstm_kernel(const float* __restrict__ x0, const float* __restrict__ x1,
                  const float* __restrict__ x2, const float* __restrict__ x3,
                  const float* __restrict__ x4, const float* __restrict__ x5,
                  const float* __restrict__ x6, const float* __restrict__ irr,
                  const float* __restrict__ Wi, const float* __restrict__ Wh,
                  const float* __restrict__ bz, const float* __restrict__ W1,
                  const float* __restrict__ b1, const float* __restrict__ W2,
                  const float* __restrict__ b2, const float* __restrict__ Wout,
                  const float* __restrict__ bout, float* __restrict__ out)
{
    extern __shared__ u64 sm[];
    u64*   hdup  = sm;                          // [136][62]: k 0-127 h dup, 128-135 features dup
    float* hnat  = (float*)(sm + 136 * HD);     // [128][60] natural h (row-pair packing)
    float* m1b   = hnat + 128 * RSTR;           // [128][60]
    float* wsm   = m1b  + 128 * RSTR;           // 2 x 8192 staging (16B aligned)
    float* cbz   = wsm  + 2 * WCH;              // 512
    float* cb1   = cbz  + 512;                  // 128
    float* cb2   = cb1  + 128;                  // 128
    float* cwo   = cb2  + 128;                  // 128
    float* red   = cwo  + 128;                  // [4][60]
    float* predb = red  + 4 * BT;               // [60]

    const int tid = threadIdx.x;
    const int lane = tid & 31;
    // z-phase mapping: 64 col-groups (2 ch), 10 row-groups (6 rows)
    const int cg  = tid & 63;
    const int rg  = tid >> 6;
    const int r0  = rg * 6;
    const int ch0 = cg << 1;
    // MLP mapping: warp = 32 channels (lane=ch), 5 row-groups (12 rows)
    const int wm   = tid >> 5;
    const int cgrp = wm & 3;
    const int rgm  = wm >> 2;
    const int mch  = (cgrp << 5) + lane;
    const int mr0  = rgm * 12;
    const int b0  = blockIdx.x * BT;

    // small constants
    for (int i = tid; i < 512; i += NT) cbz[i] = bz[i];
    if (tid < 128){ cb1[tid] = b1[tid]; cb2[tid] = b2[tid]; cwo[tid] = Wout[tid]; }
    const float boutv = bout[0];

    // feature pointers: 8 feats x 60 rows handled by tid < 480
    const int lf = tid / BT, lr = tid - lf * BT;
    const float* fptr = x0; int tmax = 0;
    if (tid < 8 * BT){
        int lb = b0 + lr; if (lb > B_TOT - 1) lb = B_TOT - 1;
        const float* p;
        if      (lf == 0) p = x0; else if (lf == 1) p = x1;
        else if (lf == 2) p = x2; else if (lf == 3) p = x3;
        else if (lf == 4) p = x4; else if (lf == 5) p = x5;
        else if (lf == 6) p = x6; else              p = irr;
        fptr = (lf < 7) ? (p + lb * T_STEPS) : (p + lb * WARM);
        tmax = (lf < 7) ? (T_STEPS - 1) : (WARM - 1);
    }

    // init h-dup = 0
    for (int i = tid; i < 128 * HD; i += NT) hdup[i] = 0ull;

    // prologue: stage Wh rows 0-15
    stage(wsm, Wh, WCH, tid);
    CPA_WAIT();
    int pb = 0;

    // c-state: per row, channel pair (c_ch0, c_ch0+1)
    u64 cst[6];
    #pragma unroll
    for (int r = 0; r < 6; r++) cst[r] = 0ull;

    __syncthreads();

    for (int t = 0; t < T_STEPS; ++t){
        // ---- stage this step's features (dup) ----
        if (tid < 8 * BT){
            int ti = t < tmax ? t : tmax;
            float gv = __ldg(fptr + ti);
            float v = (lf < 7 || t < WARM) ? gv : predb[lr];
            hdup[(128 + lf) * HD + lr] = pack2(v, v);
        }

        // ================= z = [h, feat] @ [Wh; Wi] + b =================
        // acc[row r][gate q] = (z_{q*128+ch0}, z_{q*128+ch0+1})
        u64 acc[6][4];
        #pragma unroll
        for (int q = 0; q < 4; q++){
            u64 b = *reinterpret_cast<const u64*>(cbz + (q << 7) + ch0);
            #pragma unroll
            for (int r = 0; r < 6; r++) acc[r][q] = b;
        }

        for (int c = 0; c <= 8; ++c){
            if (c < 7)       stage(wsm + ((pb ^ 1) << 13), Wh + (c + 1) * WCH, WCH, tid);
            else if (c == 7) stage(wsm + ((pb ^ 1) << 13), Wi, 4096, tid);
            else             stage(wsm + ((pb ^ 1) << 13), W1, WCH, tid);

            const float* wb = wsm + (pb << 13);
            const int nk = (c < 8) ? 16 : 8;
            const int k0 = c << 4;
            #pragma unroll 8
            for (int kk = 0; kk < nk; kk++){
                const u64* hd = hdup + (k0 + kk) * HD + r0;     // 16B aligned (HD,r0 even)
                ulonglong2 A  = *reinterpret_cast<const ulonglong2*>(hd);
                ulonglong2 Bv = *reinterpret_cast<const ulonglong2*>(hd + 2);
                ulonglong2 Cv = *reinterpret_cast<const ulonglong2*>(hd + 4);
                #pragma unroll
                for (int q = 0; q < 4; q++){
                    u64 wp = *reinterpret_cast<const u64*>(&wb[(kk << 9) + (q << 7) + ch0]);
                    acc[0][q] = fma2(A.x,  wp, acc[0][q]);
                    acc[1][q] = fma2(A.y,  wp, acc[1][q]);
                    acc[2][q] = fma2(Bv.x, wp, acc[2][q]);
                    acc[3][q] = fma2(Bv.y, wp, acc[3][q]);
                    acc[4][q] = fma2(Cv.x, wp, acc[4][q]);
                    acc[5][q] = fma2(Cv.y, wp, acc[5][q]);
                }
            }
            CPA_WAIT();
            __syncthreads();
            pb ^= 1;
        }

        // ================= gates; write h dup (for z) + natural (for MLP) =================
        float h0s[6], h1s[6];
        #pragma unroll
        for (int r = 0; r < 6; r++){
            float zi0,zi1,zf0,zf1,zg0,zg1,zo0,zo1,c0,c1;
            unpack2(acc[r][0], zi0, zi1);
            unpack2(acc[r][1], zf0, zf1);
            unpack2(acc[r][2], zg0, zg1);
            unpack2(acc[r][3], zo0, zo1);
            unpack2(cst[r], c0, c1);
            c0 = sig_(zf0)*c0 + sig_(zi0)*tanh_(zg0);
            c1 = sig_(zf1)*c1 + sig_(zi1)*tanh_(zg1);
            cst[r] = pack2(c0, c1);
            h0s[r] = sig_(zo0)*tanh_(c0);
            h1s[r] = sig_(zo1)*tanh_(c1);
            hdup[ ch0      * HD + r0 + r] = pack2(h0s[r], h0s[r]);
            hdup[(ch0 + 1) * HD + r0 + r] = pack2(h1s[r], h1s[r]);
        }
        #pragma unroll
        for (int j = 0; j < 3; j++){
            *reinterpret_cast<u64*>(&hnat[ ch0      * RSTR + r0 + (j<<1)]) = pack2(h0s[2*j], h0s[2*j+1]);
            *reinterpret_cast<u64*>(&hnat[(ch0 + 1) * RSTR + r0 + (j<<1)]) = pack2(h1s[2*j], h1s[2*j+1]);
        }
        __syncthreads();

        // ================= m1 = relu(h @ W1 + b1): lane=channel, 12 rows =================
        u64 a1[6];
        {
            float b = cb1[mch];
            u64 bb = pack2(b, b);
            #pragma unroll
            for (int j = 0; j < 6; j++) a1[j] = bb;
        }
        for (int c = 0; c < 2; ++c){
            if (c == 0) stage(wsm + ((pb ^ 1) << 13), W1 + WCH, WCH, tid);
            else        stage(wsm + ((pb ^ 1) << 13), W2, WCH, tid);

            const float* wb = wsm + (pb << 13);
            const int k0 = c << 6;
            #pragma unroll 8
            for (int kk = 0; kk < 64; kk++){
                float w = wb[(kk << 7) + mch];
                u64 wd = pack2(w, w);
                const u64* hp = reinterpret_cast<const u64*>(hnat + (k0 + kk) * RSTR + mr0);  // 16B aligned
                ulonglong2 A  = *reinterpret_cast<const ulonglong2*>(hp);
                ulonglong2 Bv = *reinterpret_cast<const ulonglong2*>(hp + 2);
                ulonglong2 Cv = *reinterpret_cast<const ulonglong2*>(hp + 4);
                a1[0] = fma2(A.x,  wd, a1[0]);
                a1[1] = fma2(A.y,  wd, a1[1]);
                a1[2] = fma2(Bv.x, wd, a1[2]);
                a1[3] = fma2(Bv.y, wd, a1[3]);
                a1[4] = fma2(Cv.x, wd, a1[4]);
                a1[5] = fma2(Cv.y, wd, a1[5]);
            }
            CPA_WAIT();
            __syncthreads();
            pb ^= 1;
        }
        #pragma unroll
        for (int j = 0; j < 6; j++){
            float v0, v1; unpack2(a1[j], v0, v1);
            *reinterpret_cast<u64*>(&m1b[mch * RSTR + mr0 + (j<<1)]) =
                pack2(fmaxf(v0, 0.f), fmaxf(v1, 0.f));
        }
        __syncthreads();

        // ================= m2 = relu(m1 @ W2 + b2) =================
        u64 a2[6];
        {
            float b = cb2[mch];
            u64 bb = pack2(b, b);
            #pragma unroll
            for (int j = 0; j < 6; j++) a2[j] = bb;
        }
        for (int c = 0; c < 2; ++c){
            if (c == 0) stage(wsm + ((pb ^ 1) << 13), W2 + WCH, WCH, tid);
            else        stage(wsm + ((pb ^ 1) << 13), Wh, WCH, tid);   // next step chunk 0

            const float* wb = wsm + (pb << 13);
            const int k0 = c << 6;
            #pragma unroll 8
            for (int kk = 0; kk < 64; kk++){
                float w = wb[(kk << 7) + mch];
                u64 wd = pack2(w, w);
                const u64* hp = reinterpret_cast<const u64*>(m1b + (k0 + kk) * RSTR + mr0);
                ulonglong2 A  = *reinterpret_cast<const ulonglong2*>(hp);
                ulonglong2 Bv = *reinterpret_cast<const ulonglong2*>(hp + 2);
                ulonglong2 Cv = *reinterpret_cast<const ulonglong2*>(hp + 4);
                a2[0] = fma2(A.x,  wd, a2[0]);
                a2[1] = fma2(A.y,  wd, a2[1]);
                a2[2] = fma2(Bv.x, wd, a2[2]);
                a2[3] = fma2(Bv.y, wd, a2[3]);
                a2[4] = fma2(Cv.x, wd, a2[4]);
                a2[5] = fma2(Cv.y, wd, a2[5]);
            }
            CPA_WAIT();
            __syncthreads();
            pb ^= 1;
        }

        // ---- out-projection: p over 12 rows, reduce across 32 channels (lanes) ----
        {
            float wo = cwo[mch];
            float p[12];
            #pragma unroll
            for (int j = 0; j < 6; j++){
                float v0, v1; unpack2(a2[j], v0, v1);
                p[(j<<1)  ] = fmaxf(v0, 0.f) * wo;
                p[(j<<1)+1] = fmaxf(v1, 0.f) * wo;
            }
            #pragma unroll
            for (int j = 0; j < 12; j++)
                #pragma unroll
                for (int off = 16; off; off >>= 1)
                    p[j] += __shfl_xor_sync(0xffffffffu, p[j], off);
            if (lane == 0){
                #pragma unroll
                for (int j = 0; j < 12; j++) red[cgrp * BT + mr0 + j] = p[j];
            }
        }
        __syncthreads();
        if (tid < BT){
            float s = boutv + red[tid] + red[BT + tid] + red[2*BT + tid] + red[3*BT + tid];
            predb[tid] = s;
            int bb = b0 + tid;
            if (bb < B_TOT) out[bb * T_STEPS + t] = s;
        }
        __syncthreads();
    }
}

extern "C" void kernel_launch(void* const* d_in, const int* in_sizes, int n_in,
                              void* d_out, int out_size)
{
    (void)in_sizes; (void)n_in; (void)out_size;
    cudaFuncSetAttribute(fused_lstm_kernel, cudaFuncAttributeMaxDynamicSharedMemorySize, SMEM_BYTES);
    int grid = (B_TOT + BT - 1) / BT; // 137
    fused_lstm_kernel<<<grid, NT, SMEM_BYTES>>>(
        (const float*)d_in[8],  (const float*)d_in[9],  (const float*)d_in[10],
        (const float*)d_in[11], (const float*)d_in[12], (const float*)d_in[13],
        (const float*)d_in[14], (const float*)d_in[15],
        (const float*)d_in[16], (const float*)d_in[17], (const float*)d_in[18],
        (const float*)d_in[19], (const float*)d_in[20], (const float*)d_in[21],
        (const float*)d_in[22], (const float*)d_in[23], (const float*)d_in[24],
        (float*)d_out);
}

// round 13
// speedup vs baseline: 1.0021x; 1.0021x over previous
#include <cuda_runtime.h>

typedef unsigned long long u64;

#define NT 640
#define BT 60
#define HD 62      /* u64 row stride, hdup */
#define RSTR 60    /* float row stride, natural (multiple of 4) */
#define B_TOT 8192
#define T_STEPS 30
#define WARM 24
#define WCH 8192   /* floats per staging chunk (32KB) */

__device__ __forceinline__ u64 pack2(float lo, float hi){
    u64 r; asm("mov.b64 %0, {%1, %2};" : "=l"(r) : "f"(lo), "f"(hi)); return r;
}
__device__ __forceinline__ void unpack2(u64 v, float& lo, float& hi){
    asm("mov.b64 {%0, %1}, %2;" : "=f"(lo), "=f"(hi) : "l"(v));
}
__device__ __forceinline__ u64 fma2(u64 a, u64 b, u64 c){
    u64 d; asm("fma.rn.f32x2 %0, %1, %2, %3;" : "=l"(d) : "l"(a), "l"(b), "l"(c)); return d;
}
__device__ __forceinline__ float sig_(float x){ return __fdividef(1.f, 1.f + __expf(-x)); }
__device__ __forceinline__ float tanh_(float x){ return 1.f - 2.f * __fdividef(1.f, __expf(2.f * x) + 1.f); }

#define CPA16(dst_u32, src) asm volatile("cp.async.cg.shared.global [%0], [%1], 16;" :: "r"(dst_u32), "l"(src))
#define CPA_COMMIT() asm volatile("cp.async.commit_group;")
#define CPA_WAIT()   asm volatile("cp.async.wait_group 0;")

__device__ __forceinline__ void stage(float* dst, const float* __restrict__ src, int nfloats, int tid){
    unsigned d = (unsigned)__cvta_generic_to_shared(dst);
    for (int i = tid; i < (nfloats >> 2); i += NT)
        CPA16(d + i * 16, src + i * 4);
    CPA_COMMIT();
}

// smem: hdup u64[136][62] | floats: hnat 128*60, m1b 128*60, wsm 2*8192, cbz 512, cb1/cb2/cwo 384, red 240, predb 60
#define SMEM_BYTES (136*HD*8 + (128*RSTR + 128*RSTR + 2*WCH + 512 + 384 + 240 + 60) * 4)

__global__ void __launch_bounds__(NT, 1)
fused_lstm_kernel(const float* __restrict__ x0, const float* __restrict__ x1,
                  const float* __restrict__ x2, const float* __restrict__ x3,
                  const float* __restrict__ x4, const float* __restrict__ x5,
                  const float* __restrict__ x6, const float* __restrict__ irr,
                  const float* __restrict__ Wi, const float* __restrict__ Wh,
                  const float* __restrict__ bz, const float* __restrict__ W1,
                  const float* __restrict__ b1, const float* __restrict__ W2,
                  const float* __restrict__ b2, const float* __restrict__ Wout,
                  const float* __restrict__ bout, float* __restrict__ out)
{
    extern __shared__ u64 sm[];
    u64*   hdup  = sm;                          // [136][62]: k 0-127 h dup, 128-135 features dup
    float* hnat  = (float*)(sm + 136 * HD);     // [128][60] natural h (row-pair packing)
    float* m1b   = hnat + 128 * RSTR;           // [128][60]
    float* wsm   = m1b  + 128 * RSTR;           // 2 x 8192 staging (16B aligned)
    float* cbz   = wsm  + 2 * WCH;              // 512
    float* cb1   = cbz  + 512;                  // 128
    float* cb2   = cb1  + 128;                  // 128
    float* cwo   = cb2  + 128;                  // 128
    float* red   = cwo  + 128;                  // [4][60]
    float* predb = red  + 4 * BT;               // [60]

    const int tid = threadIdx.x;
    const int lane = tid & 31;
    // z-phase mapping: 64 col-groups (2 ch), 10 row-groups (6 rows)
    const int cg  = tid & 63;
    const int rg  = tid >> 6;
    const int r0  = rg * 6;
    const int ch0 = cg << 1;
    // MLP mapping: warp = 32 channels (lane=ch), 5 row-groups (12 rows)
    const int wm   = tid >> 5;
    const int cgrp = wm & 3;
    const int rgm  = wm >> 2;
    const int mch  = (cgrp << 5) + lane;
    const int mr0  = rgm * 12;
    const int b0  = blockIdx.x * BT;

    // small constants
    for (int i = tid; i < 512; i += NT) cbz[i] = bz[i];
    if (tid < 128){ cb1[tid] = b1[tid]; cb2[tid] = b2[tid]; cwo[tid] = Wout[tid]; }
    const float boutv = bout[0];

    // feature pointers: 8 feats x 60 rows handled by tid < 480
    const int lf = tid / BT, lr = tid - lf * BT;
    const float* fptr = x0; int tmax = 0;
    if (tid < 8 * BT){
        int lb = b0 + lr; if (lb > B_TOT - 1) lb = B_TOT - 1;
        const float* p;
        if      (lf == 0) p = x0; else if (lf == 1) p = x1;
        else if (lf == 2) p = x2; else if (lf == 3) p = x3;
        else if (lf == 4) p = x4; else if (lf == 5) p = x5;
        else if (lf == 6) p = x6; else              p = irr;
        fptr = (lf < 7) ? (p + lb * T_STEPS) : (p + lb * WARM);
        tmax = (lf < 7) ? (T_STEPS - 1) : (WARM - 1);
    }

    // init h-dup = 0
    for (int i = tid; i < 128 * HD; i += NT) hdup[i] = 0ull;

    // prologue: stage Wh rows 0-15
    stage(wsm, Wh, WCH, tid);
    CPA_WAIT();
    int pb = 0;

    // c-state: per row, channel pair (c_ch0, c_ch0+1)
    u64 cst[6];
    #pragma unroll
    for (int r = 0; r < 6; r++) cst[r] = 0ull;

    __syncthreads();

    for (int t = 0; t < T_STEPS; ++t){
        // ---- stage this step's features (dup) ----
        if (tid < 8 * BT){
            int ti = t < tmax ? t : tmax;
            float gv = __ldg(fptr + ti);
            float v = (lf < 7 || t < WARM) ? gv : predb[lr];
            hdup[(128 + lf) * HD + lr] = pack2(v, v);
        }

        // ================= z = [h, feat] @ [Wh; Wi] + b =================
        // acc[row r][gate q] = (z_{q*128+ch0}, z_{q*128+ch0+1})
        u64 acc[6][4];
        #pragma unroll
        for (int q = 0; q < 4; q++){
            u64 b = *reinterpret_cast<const u64*>(cbz + (q << 7) + ch0);
            #pragma unroll
            for (int r = 0; r < 6; r++) acc[r][q] = b;
        }

        for (int c = 0; c <= 8; ++c){
            if (c < 7)       stage(wsm + ((pb ^ 1) << 13), Wh + (c + 1) * WCH, WCH, tid);
            else if (c == 7) stage(wsm + ((pb ^ 1) << 13), Wi, 4096, tid);
            else             stage(wsm + ((pb ^ 1) << 13), W1, WCH, tid);

            const float* wb = wsm + (pb << 13);
            const int nk = (c < 8) ? 16 : 8;
            const int k0 = c << 4;
            #pragma unroll 8
            for (int kk = 0; kk < nk; kk++){
                const u64* hd = hdup + (k0 + kk) * HD + r0;     // 16B aligned (HD,r0 even)
                ulonglong2 A  = *reinterpret_cast<const ulonglong2*>(hd);
                ulonglong2 Bv = *reinterpret_cast<const ulonglong2*>(hd + 2);
                ulonglong2 Cv = *reinterpret_cast<const ulonglong2*>(hd + 4);
                #pragma unroll
                for (int q = 0; q < 4; q++){
                    u64 wp = *reinterpret_cast<const u64*>(&wb[(kk << 9) + (q << 7) + ch0]);
                    acc[0][q] = fma2(A.x,  wp, acc[0][q]);
                    acc[1][q] = fma2(A.y,  wp, acc[1][q]);
                    acc[2][q] = fma2(Bv.x, wp, acc[2][q]);
                    acc[3][q] = fma2(Bv.y, wp, acc[3][q]);
                    acc[4][q] = fma2(Cv.x, wp, acc[4][q]);
                    acc[5][q] = fma2(Cv.y, wp, acc[5][q]);
                }
            }
            CPA_WAIT();
            __syncthreads();
            pb ^= 1;
        }

        // ================= gates; write h dup (for z) + natural (for MLP) =================
        float h0s[6], h1s[6];
        #pragma unroll
        for (int r = 0; r < 6; r++){
            float zi0,zi1,zf0,zf1,zg0,zg1,zo0,zo1,c0,c1;
            unpack2(acc[r][0], zi0, zi1);
            unpack2(acc[r][1], zf0, zf1);
            unpack2(acc[r][2], zg0, zg1);
            unpack2(acc[r][3], zo0, zo1);
            unpack2(cst[r], c0, c1);
            c0 = sig_(zf0)*c0 + sig_(zi0)*tanh_(zg0);
            c1 = sig_(zf1)*c1 + sig_(zi1)*tanh_(zg1);
            cst[r] = pack2(c0, c1);
            h0s[r] = sig_(zo0)*tanh_(c0);
            h1s[r] = sig_(zo1)*tanh_(c1);
            hdup[ ch0      * HD + r0 + r] = pack2(h0s[r], h0s[r]);
            hdup[(ch0 + 1) * HD + r0 + r] = pack2(h1s[r], h1s[r]);
        }
        #pragma unroll
        for (int j = 0; j < 3; j++){
            *reinterpret_cast<u64*>(&hnat[ ch0      * RSTR + r0 + (j<<1)]) = pack2(h0s[2*j], h0s[2*j+1]);
            *reinterpret_cast<u64*>(&hnat[(ch0 + 1) * RSTR + r0 + (j<<1)]) = pack2(h1s[2*j], h1s[2*j+1]);
        }
        __syncthreads();

        // ================= m1 = relu(h @ W1 + b1): lane=channel, 12 rows =================
        u64 a1[6];
        {
            float b = cb1[mch];
            u64 bb = pack2(b, b);
            #pragma unroll
            for (int j = 0; j < 6; j++) a1[j] = bb;
        }
        for (int c = 0; c < 2; ++c){
            if (c == 0) stage(wsm + ((pb ^ 1) << 13), W1 + WCH, WCH, tid);
            else        stage(wsm + ((pb ^ 1) << 13), W2, WCH, tid);

            const float* wb = wsm + (pb << 13);
            const int k0 = c << 6;
            #pragma unroll 8
            for (int kk = 0; kk < 64; kk++){
                float w = wb[(kk << 7) + mch];
                u64 wd = pack2(w, w);
                const u64* hp = reinterpret_cast<const u64*>(hnat + (k0 + kk) * RSTR + mr0);  // 16B aligned
                ulonglong2 A  = *reinterpret_cast<const ulonglong2*>(hp);
                ulonglong2 Bv = *reinterpret_cast<const ulonglong2*>(hp + 2);
                ulonglong2 Cv = *reinterpret_cast<const ulonglong2*>(hp + 4);
                a1[0] = fma2(A.x,  wd, a1[0]);
                a1[1] = fma2(A.y,  wd, a1[1]);
                a1[2] = fma2(Bv.x, wd, a1[2]);
                a1[3] = fma2(Bv.y, wd, a1[3]);
                a1[4] = fma2(Cv.x, wd, a1[4]);
                a1[5] = fma2(Cv.y, wd, a1[5]);
            }
            CPA_WAIT();
            __syncthreads();
            pb ^= 1;
        }
        #pragma unroll
        for (int j = 0; j < 6; j++){
            float v0, v1; unpack2(a1[j], v0, v1);
            *reinterpret_cast<u64*>(&m1b[mch * RSTR + mr0 + (j<<1)]) =
                pack2(fmaxf(v0, 0.f), fmaxf(v1, 0.f));
        }
        __syncthreads();

        // ================= m2 = relu(m1 @ W2 + b2) =================
        u64 a2[6];
        {
            float b = cb2[mch];
            u64 bb = pack2(b, b);
            #pragma unroll
            for (int j = 0; j < 6; j++) a2[j] = bb;
        }
        for (int c = 0; c < 2; ++c){
            if (c == 0) stage(wsm + ((pb ^ 1) << 13), W2 + WCH, WCH, tid);
            else        stage(wsm + ((pb ^ 1) << 13), Wh, WCH, tid);   // next step chunk 0

            const float* wb = wsm + (pb << 13);
            const int k0 = c << 6;
            #pragma unroll 8
            for (int kk = 0; kk < 64; kk++){
                float w = wb[(kk << 7) + mch];
                u64 wd = pack2(w, w);
                const u64* hp = reinterpret_cast<const u64*>(m1b + (k0 + kk) * RSTR + mr0);
                ulonglong2 A  = *reinterpret_cast<const ulonglong2*>(hp);
                ulonglong2 Bv = *reinterpret_cast<const ulonglong2*>(hp + 2);
                ulonglong2 Cv = *reinterpret_cast<const ulonglong2*>(hp + 4);
                a2[0] = fma2(A.x,  wd, a2[0]);
                a2[1] = fma2(A.y,  wd, a2[1]);
                a2[2] = fma2(Bv.x, wd, a2[2]);
                a2[3] = fma2(Bv.y, wd, a2[3]);
                a2[4] = fma2(Cv.x, wd, a2[4]);
                a2[5] = fma2(Cv.y, wd, a2[5]);
            }
            CPA_WAIT();
            __syncthreads();
            pb ^= 1;
        }

        // ---- out-projection: p over 12 rows, reduce across 32 channels (lanes) ----
        {
            float wo = cwo[mch];
            float p[12];
            #pragma unroll
            for (int j = 0; j < 6; j++){
                float v0, v1; unpack2(a2[j], v0, v1);
                p[(j<<1)  ] = fmaxf(v0, 0.f) * wo;
                p[(j<<1)+1] = fmaxf(v1, 0.f) * wo;
            }
            #pragma unroll
            for (int j = 0; j < 12; j++)
                #pragma unroll
                for (int off = 16; off; off >>= 1)
                    p[j] += __shfl_xor_sync(0xffffffffu, p[j], off);
            if (lane == 0){
                #pragma unroll
                for (int j = 0; j < 12; j++) red[cgrp * BT + mr0 + j] = p[j];
            }
        }
        __syncthreads();
        if (tid < BT){
            float s = boutv + red[tid] + red[BT + tid] + red[2*BT + tid] + red[3*BT + tid];
            predb[tid] = s;
            int bb = b0 + tid;
            if (bb < B_TOT) out[bb * T_STEPS + t] = s;
        }
        __syncthreads();
    }
}

extern "C" void kernel_launch(void* const* d_in, const int* in_sizes, int n_in,
                              void* d_out, int out_size)
{
    (void)in_sizes; (void)n_in; (void)out_size;
    cudaFuncSetAttribute(fused_lstm_kernel, cudaFuncAttributeMaxDynamicSharedMemorySize, SMEM_BYTES);
    int grid = (B_TOT + BT - 1) / BT; // 137
    fused_lstm_kernel<<<grid, NT, SMEM_BYTES>>>(
        (const float*)d_in[8],  (const float*)d_in[9],  (const float*)d_in[10],
        (const float*)d_in[11], (const float*)d_in[12], (const float*)d_in[13],
        (const float*)d_in[14], (const float*)d_in[15],
        (const float*)d_in[16], (const float*)d_in[17], (const float*)d_in[18],
        (const float*)d_in[19], (const float*)d_in[20], (const float*)d_in[21],
        (const float*)d_in[22], (const float*)d_in[23], (const float*)d_in[24],
        (float*)d_out);
}

// round 14
// speedup vs baseline: 1.1636x; 1.1611x over previous
#include <cuda_runtime.h>

typedef unsigned long long u64;

#define NT 640
#define BT 60
#define RSTR 62
#define B_TOT 8192
#define T_STEPS 30
#define WARM 24
#define WCH 8192

__device__ __forceinline__ u64 pack2(float lo, float hi){
    u64 r; asm("mov.b64 %0, {%1, %2};" : "=l"(r) : "f"(lo), "f"(hi)); return r;
}
__device__ __forceinline__ void unpack2(u64 v, float& lo, float& hi){
    asm("mov.b64 {%0, %1}, %2;" : "=f"(lo), "=f"(hi) : "l"(v));
}
__device__ __forceinline__ u64 fma2(u64 a, u64 b, u64 c){
    u64 d; asm("fma.rn.f32x2 %0, %1, %2, %3;" : "=l"(d) : "l"(a), "l"(b), "l"(c)); return d;
}
__device__ __forceinline__ float sig_(float x){ return __fdividef(1.f, 1.f + __expf(-x)); }
__device__ __forceinline__ float tanh_(float x){ return 1.f - 2.f * __fdividef(1.f, __expf(2.f * x) + 1.f); }

#define CPA16(dst_u32, src) asm volatile("cp.async.cg.shared.global [%0], [%1], 16;" :: "r"(dst_u32), "l"(src))
#define CPA_COMMIT() asm volatile("cp.async.commit_group;")
#define CPA_WAIT()   asm volatile("cp.async.wait_group 0;")

__device__ __forceinline__ void stage(float* dst, const float* __restrict__ src, int nfloats, int tid){
    unsigned d = (unsigned)__cvta_generic_to_shared(dst);
    for (int i = tid; i < (nfloats >> 2); i += NT)
        CPA16(d + i * 16, src + i * 4);
    CPA_COMMIT();
}

#define SMEM_FLOATS (2*WCH + 136*RSTR + 128*RSTR + 512 + 384 + 2*BT + BT)
#define SMEM_BYTES (SMEM_FLOATS * 4)

__global__ void __launch_bounds__(NT, 1)
fused_lstm_kernel(const float* __restrict__ x0, const float* __restrict__ x1,
                  const float* __restrict__ x2, const float* __restrict__ x3,
                  const float* __restrict__ x4, const float* __restrict__ x5,
                  const float* __restrict__ x6, const float* __restrict__ irr,
                  const float* __restrict__ Wi, const float* __restrict__ Wh,
                  const float* __restrict__ bz, const float* __restrict__ W1,
                  const float* __restrict__ b1, const float* __restrict__ W2,
                  const float* __restrict__ b2, const float* __restrict__ Wout,
                  const float* __restrict__ bout, float* __restrict__ out)
{
    extern __shared__ float smem[];
    float* wsm   = smem;                  // 2 x 8192 weight staging (z only)
    float* hbuf  = wsm   + 2 * WCH;       // [136][62]: rows 0-127 h, 128-135 inputs
    float* m1buf = hbuf  + 136 * RSTR;    // [128][62]
    float* cbz   = m1buf + 128 * RSTR;    // 512
    float* cb1   = cbz   + 512;           // 128
    float* cb2   = cb1   + 128;           // 128
    float* cwo   = cb2   + 128;           // 128
    float* red   = cwo   + 128;           // [2][60]
    float* predb = red   + 2 * BT;        // [60]

    const int tid = threadIdx.x;
    const int rg  = tid >> 6;             // 0..9, 6 rows each
    const int cg  = tid & 63;             // 0..63, 2 channels each
    const int r0  = rg * 6;
    const int ch0 = cg << 1;
    const int b0  = blockIdx.x * BT;

    for (int i = tid; i < 512; i += NT) cbz[i] = bz[i];
    if (tid < 128){ cb1[tid] = b1[tid]; cb2[tid] = b2[tid]; cwo[tid] = Wout[tid]; }
    const float boutv = bout[0];

    const int lf = tid / BT, lr = tid - lf * BT;
    const float* fptr = x0; int tmax = 0;
    if (tid < 8 * BT){
        int lb = b0 + lr; if (lb > B_TOT - 1) lb = B_TOT - 1;
        const float* p;
        if      (lf == 0) p = x0; else if (lf == 1) p = x1;
        else if (lf == 2) p = x2; else if (lf == 3) p = x3;
        else if (lf == 4) p = x4; else if (lf == 5) p = x5;
        else if (lf == 6) p = x6; else              p = irr;
        fptr = (lf < 7) ? (p + lb * T_STEPS) : (p + lb * WARM);
        tmax = (lf < 7) ? (T_STEPS - 1) : (WARM - 1);
    }

    for (int i = tid; i < 128 * RSTR; i += NT) hbuf[i] = 0.f;

    stage(wsm, Wh, WCH, tid);
    CPA_WAIT();
    int pb = 0;

    u64 cst[3][2];
    #pragma unroll
    for (int rp = 0; rp < 3; rp++){ cst[rp][0] = 0ull; cst[rp][1] = 0ull; }

    __syncthreads();

    for (int t = 0; t < T_STEPS; ++t){
        if (tid < 8 * BT){
            int ti = t < tmax ? t : tmax;
            float gv = __ldg(fptr + ti);
            float v = (lf < 7 || t < WARM) ? gv : predb[lr];
            hbuf[(128 + lf) * RSTR + lr] = v;
        }

        // ================= z = [h, inp] @ [Wh; Wi] + b =================
        u64 acc[3][8];
        #pragma unroll
        for (int q = 0; q < 4; q++)
            #pragma unroll
            for (int d = 0; d < 2; d++){
                float bv = cbz[(q << 7) + ch0 + d];
                u64 p = pack2(bv, bv);
                acc[0][(q<<1)+d] = p; acc[1][(q<<1)+d] = p; acc[2][(q<<1)+d] = p;
            }

        // 9 chunks: c0..7 = Wh rows 16c..16c+15, c8 = Wi; c8 prefetches NEXT step's Wh c0
        for (int c = 0; c <= 8; ++c){
            if (c < 7)       stage(wsm + ((pb ^ 1) << 13), Wh + (c + 1) * WCH, WCH, tid);
            else if (c == 7) stage(wsm + ((pb ^ 1) << 13), Wi, 4096, tid);
            else             stage(wsm + ((pb ^ 1) << 13), Wh, WCH, tid);

            const float* wb = wsm + (pb << 13);
            const int nk = (c < 8) ? 16 : 8;
            const int k0 = c << 4;
            #pragma unroll 8
            for (int kk = 0; kk < nk; kk++){
                const u64* h64 = reinterpret_cast<const u64*>(hbuf + (k0 + kk) * RSTR + r0);
                u64 hp0 = h64[0], hp1 = h64[1], hp2 = h64[2];
                #pragma unroll
                for (int q = 0; q < 4; q++){
                    u64 wp = *reinterpret_cast<const u64*>(&wb[(kk << 9) + (q << 7) + ch0]);
                    float w0, w1; unpack2(wp, w0, w1);
                    u64 w00 = pack2(w0, w0), w11 = pack2(w1, w1);
                    acc[0][(q<<1)]   = fma2(hp0, w00, acc[0][(q<<1)]);
                    acc[1][(q<<1)]   = fma2(hp1, w00, acc[1][(q<<1)]);
                    acc[2][(q<<1)]   = fma2(hp2, w00, acc[2][(q<<1)]);
                    acc[0][(q<<1)+1] = fma2(hp0, w11, acc[0][(q<<1)+1]);
                    acc[1][(q<<1)+1] = fma2(hp1, w11, acc[1][(q<<1)+1]);
                    acc[2][(q<<1)+1] = fma2(hp2, w11, acc[2][(q<<1)+1]);
                }
            }
            CPA_WAIT();
            __syncthreads();
            pb ^= 1;
        }

        // ================= gates =================
        #pragma unroll
        for (int rp = 0; rp < 3; rp++)
            #pragma unroll
            for (int d = 0; d < 2; d++){
                float zi0,zi1,zf0,zf1,zg0,zg1,zo0,zo1,c0,c1;
                unpack2(acc[rp][0+d], zi0, zi1);
                unpack2(acc[rp][2+d], zf0, zf1);
                unpack2(acc[rp][4+d], zg0, zg1);
                unpack2(acc[rp][6+d], zo0, zo1);
                unpack2(cst[rp][d], c0, c1);
                c0 = sig_(zf0)*c0 + sig_(zi0)*tanh_(zg0);
                c1 = sig_(zf1)*c1 + sig_(zi1)*tanh_(zg1);
                cst[rp][d] = pack2(c0, c1);
                float h0 = sig_(zo0)*tanh_(c0);
                float h1 = sig_(zo1)*tanh_(c1);
                *reinterpret_cast<u64*>(&hbuf[(ch0+d)*RSTR + r0 + (rp<<1)]) = pack2(h0, h1);
            }
        __syncthreads();

        // ================= m1 = relu(h @ W1 + b1), weights via LDG (L1) =================
        u64 a1[3][2];
        {
            float q0 = cb1[ch0], q1 = cb1[ch0 + 1];
            u64 p0 = pack2(q0,q0), p1 = pack2(q1,q1);
            a1[0][0]=p0; a1[1][0]=p0; a1[2][0]=p0;
            a1[0][1]=p1; a1[1][1]=p1; a1[2][1]=p1;
        }
        {
            const float* wr = W1 + ch0;
            #pragma unroll 8
            for (int k = 0; k < 128; k++){
                const u64* h64 = reinterpret_cast<const u64*>(hbuf + k * RSTR + r0);
                u64 hp0 = h64[0], hp1 = h64[1], hp2 = h64[2];
                u64 wp = *reinterpret_cast<const u64*>(wr + (k << 7));
                float w0, w1; unpack2(wp, w0, w1);
                u64 w00 = pack2(w0, w0), w11 = pack2(w1, w1);
                a1[0][0] = fma2(hp0, w00, a1[0][0]);
                a1[1][0] = fma2(hp1, w00, a1[1][0]);
                a1[2][0] = fma2(hp2, w00, a1[2][0]);
                a1[0][1] = fma2(hp0, w11, a1[0][1]);
                a1[1][1] = fma2(hp1, w11, a1[1][1]);
                a1[2][1] = fma2(hp2, w11, a1[2][1]);
            }
        }
        #pragma unroll
        for (int rp = 0; rp < 3; rp++)
            #pragma unroll
            for (int d = 0; d < 2; d++){
                float v0, v1; unpack2(a1[rp][d], v0, v1);
                *reinterpret_cast<u64*>(&m1buf[(ch0+d)*RSTR + r0 + (rp<<1)]) =
                    pack2(fmaxf(v0, 0.f), fmaxf(v1, 0.f));
            }
        __syncthreads();

        // ================= m2 = relu(m1 @ W2 + b2), weights via LDG =================
        u64 a2[3][2];
        {
            float q0 = cb2[ch0], q1 = cb2[ch0 + 1];
            u64 p0 = pack2(q0,q0), p1 = pack2(q1,q1);
            a2[0][0]=p0; a2[1][0]=p0; a2[2][0]=p0;
            a2[0][1]=p1; a2[1][1]=p1; a2[2][1]=p1;
        }
        {
            const float* wr = W2 + ch0;
            #pragma unroll 8
            for (int k = 0; k < 128; k++){
                const u64* h64 = reinterpret_cast<const u64*>(m1buf + k * RSTR + r0);
                u64 hp0 = h64[0], hp1 = h64[1], hp2 = h64[2];
                u64 wp = *reinterpret_cast<const u64*>(wr + (k << 7));
                float w0, w1; unpack2(wp, w0, w1);
                u64 w00 = pack2(w0, w0), w11 = pack2(w1, w1);
                a2[0][0] = fma2(hp0, w00, a2[0][0]);
                a2[1][0] = fma2(hp1, w00, a2[1][0]);
                a2[2][0] = fma2(hp2, w00, a2[2][0]);
                a2[0][1] = fma2(hp0, w11, a2[0][1]);
                a2[1][1] = fma2(hp1, w11, a2[1][1]);
                a2[2][1] = fma2(hp2, w11, a2[2][1]);
            }
        }

        // ---- out-projection + warp shuffle reduce ----
        float p[6];
        {
            float wo0 = cwo[ch0], wo1 = cwo[ch0 + 1];
            #pragma unroll
            for (int rp = 0; rp < 3; rp++){
                float v0a, v0b, v1a, v1b;
                unpack2(a2[rp][0], v0a, v0b);
                unpack2(a2[rp][1], v1a, v1b);
                p[(rp<<1)  ] = fmaxf(v0a, 0.f) * wo0 + fmaxf(v1a, 0.f) * wo1;
                p[(rp<<1)+1] = fmaxf(v0b, 0.f) * wo0 + fmaxf(v1b, 0.f) * wo1;
            }
        }
        #pragma unroll
        for (int j = 0; j < 6; j++)
            #pragma unroll
            for (int off = 16; off; off >>= 1)
                p[j] += __shfl_xor_sync(0xffffffffu, p[j], off);
        if ((tid & 31) == 0){
            int half = (tid >> 5) & 1;
            #pragma unroll
            for (int j = 0; j < 6; j++) red[half * BT + r0 + j] = p[j];
        }
        __syncthreads();
        if (tid < BT){
            float s = boutv + red[tid] + red[BT + tid];
            predb[tid] = s;
            int bb = b0 + tid;
            if (bb < B_TOT) out[bb * T_STEPS + t] = s;
        }
        __syncthreads();
    }
}

extern "C" void kernel_launch(void* const* d_in, const int* in_sizes, int n_in,
                              void* d_out, int out_size)
{
    (void)in_sizes; (void)n_in; (void)out_size;
    cudaFuncSetAttribute(fused_lstm_kernel, cudaFuncAttributeMaxDynamicSharedMemorySize, SMEM_BYTES);
    int grid = (B_TOT + BT - 1) / BT; // 137
    fused_lstm_kernel<<<grid, NT, SMEM_BYTES>>>(
        (const float*)d_in[8],  (const float*)d_in[9],  (const float*)d_in[10],
        (const float*)d_in[11], (const float*)d_in[12], (const float*)d_in[13],
        (const float*)d_in[14], (const float*)d_in[15],
        (const float*)d_in[16], (const float*)d_in[17], (const float*)d_in[18],
        (const float*)d_in[19], (const float*)d_in[20], (const float*)d_in[21],
        (const float*)d_in[22], (const float*)d_in[23], (const float*)d_in[24],
        (float*)d_out);
}

// round 16
// speedup vs baseline: 1.9513x; 1.6770x over previous
#include <cuda_runtime.h>
#include <cuda_bf16.h>
#include <cstdint>
typedef unsigned u32; typedef unsigned long long u64; typedef uint16_t u16;

#define TS 30
#define WARM 24
#define B_TOT 8192

__device__ u32 gZh[36864], gZl[36864];
__device__ u32 g1h[9216], g1l[9216], g2h[9216], g2l[9216];

// ---------------- prep: weights -> bf16 hi/lo in B-fragment order ----------------
__global__ void prep(const float* __restrict__ Wi, const float* __restrict__ Wh,
                     const float* __restrict__ bz, const float* __restrict__ W1,
                     const float* __restrict__ b1, const float* __restrict__ W2,
                     const float* __restrict__ b2){
    int idx = blockIdx.x*256 + threadIdx.x;
    const float *W=0, *bb=0; u32 *dh, *dl; int nts;
    if (idx < 36864){ nts=64; dh=gZh; dl=gZl; }
    else if (idx < 46080){ idx-=36864; nts=16; W=W1; bb=b1; dh=g1h; dl=g1l; }
    else if (idx < 55296){ idx-=46080; nts=16; W=W2; bb=b2; dh=g2h; dl=g2l; }
    else return;
    int fz = idx>>6, rem = idx&63, lane = rem>>1, reg = rem&1;
    int kt = fz/nts, ntg = fz%nts;
    int n = ntg*8 + (lane>>2);
    int k0 = kt*16 + 2*(lane&3) + reg*8;
    float v[2];
    #pragma unroll
    for (int e=0;e<2;e++){
        int k = k0+e; float x = 0.f;
        if (nts==64){
            int col = ((n&3)<<7) + (n>>2);     // z col n = 4*ch+gate
            if (k<128) x = Wh[k*512+col];
            else if (k<136) x = Wi[(k-128)*512+col];
            else if (k==136) x = bz[col];
        } else {
            if (k<128) x = W[k*128+n];
            else if (k==136) x = bb[n];
        }
        v[e] = x;
    }
    __nv_bfloat16 h0=__float2bfloat16(v[0]), h1=__float2bfloat16(v[1]);
    __nv_bfloat16 l0=__float2bfloat16(v[0]-__bfloat162float(h0));
    __nv_bfloat16 l1=__float2bfloat16(v[1]-__bfloat162float(h1));
    dh[fz*64+rem] = ((u32)(*(u16*)&h1)<<16) | (*(u16*)&h0);
    dl[fz*64+rem] = ((u32)(*(u16*)&l1)<<16) | (*(u16*)&l0);
}

__device__ __forceinline__ float sig_(float x){ return __fdividef(1.f, 1.f+__expf(-x)); }
__device__ __forceinline__ float th_(float x){ return 1.f - 2.f*__fdividef(1.f, __expf(2.f*x)+1.f); }
__device__ __forceinline__ void mma_(float* c, const u32* a, u32 b0, u32 b1){
    asm volatile("mma.sync.aligned.m16n8k16.row.col.f32.bf16.bf16.f32 "
        "{%0,%1,%2,%3},{%4,%5,%6,%7},{%8,%9},{%0,%1,%2,%3};"
        : "+f"(c[0]),"+f"(c[1]),"+f"(c[2]),"+f"(c[3])
        : "r"(a[0]),"r"(a[1]),"r"(a[2]),"r"(a[3]),"r"(b0),"r"(b1));
}
__device__ __forceinline__ void split2(float a, float b, u32& hi, u32& lo){
    __nv_bfloat16 ah=__float2bfloat16(a), bh=__float2bfloat16(b);
    __nv_bfloat16 al=__float2bfloat16(a-__bfloat162float(ah));
    __nv_bfloat16 bl=__float2bfloat16(b-__bfloat162float(bh));
    hi = ((u32)(*(u16*)&bh)<<16) | (*(u16*)&ah);
    lo = ((u32)(*(u16*)&bl)<<16) | (*(u16*)&al);
}
// A tile u32 layout: [kt][row][kp_perm]  kp_perm = (kp&3)*2 + (kp>>2); frag = 2 x LDS.64
#define AIDX(kt,row,kpp) ((kt)*512 + (row)*8 + (kpp))

#define SMEM_BYTES (27648*4 + (512+64+128)*4)

__global__ void __launch_bounds__(256,1)
lstm_mma(const float* __restrict__ x0, const float* __restrict__ x1, const float* __restrict__ x2,
         const float* __restrict__ x3, const float* __restrict__ x4, const float* __restrict__ x5,
         const float* __restrict__ x6, const float* __restrict__ irr,
         const float* __restrict__ Wout, const float* __restrict__ bout, float* __restrict__ out)
{
    extern __shared__ u32 sm[];
    // A buffers: [buf][hi 4608 | lo 4608], M: hi/lo
    u32* Mh = sm + 18432; u32* Ml = Mh + 4608;
    float* red   = (float*)(Ml + 4608);   // [8][64]
    float* predb = red + 512;             // [64]
    float* woS   = predb + 64;            // [128]

    const int tid=threadIdx.x, lane=tid&31, w=tid>>5, g=lane>>2, l4=lane&3;
    const int b0 = blockIdx.x*64;
    const float* xs0=x0; const float* xs1=x1; const float* xs2=x2; const float* xs3=x3;
    const float* xs4=x4; const float* xs5=x5; const float* xs6=x6;

    for (int i=tid;i<27648;i+=256) sm[i]=0;
    if (tid<128) woS[tid]=Wout[tid];
    const float boutv = bout[0];
    __syncthreads();
    if (tid<64){ // bias col 136 -> kt8, kp 4 -> perm 1, byte 0
        ((u16*)(sm        ))[(AIDX(8,tid,1))*2] = 0x3F80;
        ((u16*)(sm +  9216))[(AIDX(8,tid,1))*2] = 0x3F80;
        ((u16*)Mh)[(AIDX(8,tid,1))*2] = 0x3F80;
    }
    // features t=0: thread -> (fp=tid>>6, row=tid&63), cols 128+2fp,129+2fp -> kp fp -> perm 2fp
    {
        int fp=tid>>6, row=tid&63, gb=b0+row;
        float v0, v1;
        int f0=2*fp, f1=f0+1;
        const float* pa = (f0==0)?xs0:(f0==2)?xs2:(f0==4)?xs4:xs6;
        const float* pb = (f1==1)?xs1:(f1==3)?xs3:(f1==5)?xs5:0;
        v0 = __ldg(pa + gb*TS);
        v1 = (f1<7) ? __ldg(pb + gb*TS) : __ldg(irr + gb*WARM);
        u32 hi,lo; split2(v0,v1,hi,lo);
        sm[AIDX(8,row,2*fp)] = hi; sm[9216 + AIDX(8,row,2*fp)] = lo;
    }
    float cst[64];
    #pragma unroll
    for (int i=0;i<64;i++) cst[i]=0.f;
    int p = 0;
    __syncthreads();

    for (int t=0; t<TS; t++){
        const u32* Ah = sm + p*9216; const u32* Al = Ah + 4608;
        u32* NAh = sm + (p^1)*9216;  u32* NAl = NAh + 4608;

        // =================== z GEMM (two N-halves) + gates ===================
        #pragma unroll
        for (int half=0; half<2; half++){
            float acc[4][4][4];
            #pragma unroll
            for (int a_=0;a_<4;a_++)
                #pragma unroll
                for (int b_=0;b_<4;b_++){ acc[a_][b_][0]=0;acc[a_][b_][1]=0;acc[a_][b_][2]=0;acc[a_][b_][3]=0; }
            for (int kt=0; kt<9; kt++){
                u32 ah[4][4], al[4][4];
                #pragma unroll
                for (int mt=0;mt<4;mt++){
                    int base = AIDX(kt, mt*16+g, 2*l4);
                    u64 va = *(const u64*)(Ah+base), vb = *(const u64*)(Ah+base+64);
                    ah[mt][0]=(u32)va; ah[mt][2]=(u32)(va>>32);
                    ah[mt][1]=(u32)vb; ah[mt][3]=(u32)(vb>>32);
                    u64 vc = *(const u64*)(Al+base), vd = *(const u64*)(Al+base+64);
                    al[mt][0]=(u32)vc; al[mt][2]=(u32)(vc>>32);
                    al[mt][1]=(u32)vd; al[mt][3]=(u32)(vd>>32);
                }
                #pragma unroll
                for (int nt=0;nt<4;nt++){
                    int ntg = w*8 + half*4 + nt;
                    u64 vh = ((const u64*)gZh)[(kt*64+ntg)*32 + lane];
                    u64 vl = ((const u64*)gZl)[(kt*64+ntg)*32 + lane];
                    #pragma unroll
                    for (int mt=0;mt<4;mt++){
                        mma_(acc[nt][mt], ah[mt], (u32)vh, (u32)(vh>>32));
                        mma_(acc[nt][mt], al[mt], (u32)vh, (u32)(vh>>32));
                        mma_(acc[nt][mt], ah[mt], (u32)vl, (u32)(vl>>32));
                    }
                }
            }
            // gates: lane pair (lane^1) exchange; write h (hi by even, lo by odd) into next A buf
            #pragma unroll
            for (int nt=0;nt<4;nt++){
                int kpp = nt*2 + half;                       // perm of kp=half*4+nt
                #pragma unroll
                for (int mt=0;mt<4;mt++){
                    float* c = acc[nt][mt];
                    float t0=__shfl_xor_sync(0xffffffffu,c[0],1);
                    float t1=__shfl_xor_sync(0xffffffffu,c[1],1);
                    float t2=__shfl_xor_sync(0xffffffffu,c[2],1);
                    float t3=__shfl_xor_sync(0xffffffffu,c[3],1);
                    bool odd = (l4&1);
                    float zi0=odd?t0:c[0], zf0=odd?t1:c[1], zg0=odd?c[0]:t0, zo0=odd?c[1]:t1;
                    float zi1=odd?t2:c[2], zf1=odd?t3:c[3], zg1=odd?c[2]:t2, zo1=odd?c[3]:t3;
                    int ci = half*32 + nt*8 + mt*2;
                    float cc0 = sig_(zf0)*cst[ci]   + sig_(zi0)*th_(zg0);
                    float cc1 = sig_(zf1)*cst[ci+1] + sig_(zi1)*th_(zg1);
                    cst[ci]=cc0; cst[ci+1]=cc1;
                    float h0 = sig_(zo0)*th_(cc0), h1 = sig_(zo1)*th_(cc1);
                    int row = mt*16+g, byte = l4>>1;
                    u16* dst = odd ? (u16*)NAl : (u16*)NAh;
                    __nv_bfloat16 e0=__float2bfloat16(h0);
                    __nv_bfloat16 e1=__float2bfloat16(h1);
                    if (odd){ e0=__float2bfloat16(h0-__bfloat162float(__float2bfloat16(h0)));
                              e1=__float2bfloat16(h1-__bfloat162float(__float2bfloat16(h1))); }
                    dst[(AIDX(w,row,  kpp))*2 + byte] = *(u16*)&e0;
                    dst[(AIDX(w,row+8,kpp))*2 + byte] = *(u16*)&e1;
                }
            }
        }
        __syncthreads();   // new h complete in NA

        // =================== m1 = relu(h@W1+b1) -> M tiles ===================
        {
            float acc[2][4][4];
            #pragma unroll
            for (int a_=0;a_<2;a_++)
                #pragma unroll
                for (int b_=0;b_<4;b_++){ acc[a_][b_][0]=0;acc[a_][b_][1]=0;acc[a_][b_][2]=0;acc[a_][b_][3]=0; }
            for (int kt=0; kt<9; kt++){
                u32 ah[4][4], al[4][4];
                #pragma unroll
                for (int mt=0;mt<4;mt++){
                    int base = AIDX(kt, mt*16+g, 2*l4);
                    u64 va = *(const u64*)(NAh+base), vb = *(const u64*)(NAh+base+64);
                    ah[mt][0]=(u32)va; ah[mt][2]=(u32)(va>>32);
                    ah[mt][1]=(u32)vb; ah[mt][3]=(u32)(vb>>32);
                    u64 vc = *(const u64*)(NAl+base), vd = *(const u64*)(NAl+base+64);
                    al[mt][0]=(u32)vc; al[mt][2]=(u32)(vc>>32);
                    al[mt][1]=(u32)vd; al[mt][3]=(u32)(vd>>32);
                }
                #pragma unroll
                for (int nt=0;nt<2;nt++){
                    int ntg = w*2 + nt;
                    u64 vh = ((const u64*)g1h)[(kt*16+ntg)*32 + lane];
                    u64 vl = ((const u64*)g1l)[(kt*16+ntg)*32 + lane];
                    #pragma unroll
                    for (int mt=0;mt<4;mt++){
                        mma_(acc[nt][mt], ah[mt], (u32)vh, (u32)(vh>>32));
                        mma_(acc[nt][mt], al[mt], (u32)vh, (u32)(vh>>32));
                        mma_(acc[nt][mt], ah[mt], (u32)vl, (u32)(vl>>32));
                    }
                }
            }
            #pragma unroll
            for (int nt=0;nt<2;nt++)
                #pragma unroll
                for (int mt=0;mt<4;mt++){
                    float* c = acc[nt][mt];
                    int row = mt*16+g, kpp = l4*2+nt;
                    u32 hi,lo;
                    split2(fmaxf(c[0],0.f), fmaxf(c[1],0.f), hi, lo);
                    Mh[AIDX(w,row,kpp)] = hi; Ml[AIDX(w,row,kpp)] = lo;
                    split2(fmaxf(c[2],0.f), fmaxf(c[3],0.f), hi, lo);
                    Mh[AIDX(w,row+8,kpp)] = hi; Ml[AIDX(w,row+8,kpp)] = lo;
                }
        }
        __syncthreads();

        // =================== m2 + out-projection ===================
        {
            float acc[2][4][4];
            #pragma unroll
            for (int a_=0;a_<2;a_++)
                #pragma unroll
                for (int b_=0;b_<4;b_++){ acc[a_][b_][0]=0;acc[a_][b_][1]=0;acc[a_][b_][2]=0;acc[a_][b_][3]=0; }
            for (int kt=0; kt<9; kt++){
                u32 ah[4][4], al[4][4];
                #pragma unroll
                for (int mt=0;mt<4;mt++){
                    int base = AIDX(kt, mt*16+g, 2*l4);
                    u64 va = *(const u64*)(Mh+base), vb = *(const u64*)(Mh+base+64);
                    ah[mt][0]=(u32)va; ah[mt][2]=(u32)(va>>32);
                    ah[mt][1]=(u32)vb; ah[mt][3]=(u32)(vb>>32);
                    u64 vc = *(const u64*)(Ml+base), vd = *(const u64*)(Ml+base+64);
                    al[mt][0]=(u32)vc; al[mt][2]=(u32)(vc>>32);
                    al[mt][1]=(u32)vd; al[mt][3]=(u32)(vd>>32);
                }
                #pragma unroll
                for (int nt=0;nt<2;nt++){
                    int ntg = w*2 + nt;
                    u64 vh = ((const u64*)g2h)[(kt*16+ntg)*32 + lane];
                    u64 vl = ((const u64*)g2l)[(kt*16+ntg)*32 + lane];
                    #pragma unroll
                    for (int mt=0;mt<4;mt++){
                        mma_(acc[nt][mt], ah[mt], (u32)vh, (u32)(vh>>32));
                        mma_(acc[nt][mt], al[mt], (u32)vh, (u32)(vh>>32));
                        mma_(acc[nt][mt], ah[mt], (u32)vl, (u32)(vl>>32));
                    }
                }
            }
            #pragma unroll
            for (int mt=0;mt<4;mt++){
                float p0=0.f, p1=0.f;
                #pragma unroll
                for (int nt=0;nt<2;nt++){
                    int n = w*16 + nt*8 + 2*l4;
                    float* c = acc[nt][mt];
                    p0 += fmaxf(c[0],0.f)*woS[n] + fmaxf(c[1],0.f)*woS[n+1];
                    p1 += fmaxf(c[2],0.f)*woS[n] + fmaxf(c[3],0.f)*woS[n+1];
                }
                p0 += __shfl_xor_sync(0xffffffffu,p0,1); p0 += __shfl_xor_sync(0xffffffffu,p0,2);
                p1 += __shfl_xor_sync(0xffffffffu,p1,1); p1 += __shfl_xor_sync(0xffffffffu,p1,2);
                if (l4==0){ red[w*64 + mt*16+g] = p0; red[w*64 + mt*16+g+8] = p1; }
            }
        }
        __syncthreads();
        if (tid < 64){
            float s = boutv;
            #pragma unroll
            for (int j=0;j<8;j++) s += red[j*64+tid];
            predb[tid] = s;
            out[(size_t)(b0+tid)*TS + t] = s;
        }
        __syncthreads();
        // features for t+1 -> next A buffer
        if (t+1 < TS){
            int fp=tid>>6, row=tid&63, gb=b0+row;
            int f0=2*fp, f1=f0+1;
            const float* pa = (f0==0)?xs0:(f0==2)?xs2:(f0==4)?xs4:xs6;
            const float* pb = (f1==1)?xs1:(f1==3)?xs3:(f1==5)?xs5:0;
            float v0 = __ldg(pa + gb*TS + t+1);
            float v1 = (f1<7) ? __ldg(pb + gb*TS + t+1)
                              : ((t+1<WARM) ? __ldg(irr + gb*WARM + t+1) : predb[row]);
            u32 hi,lo; split2(v0,v1,hi,lo);
            NAh[AIDX(8,row,2*fp)] = hi; NAl[AIDX(8,row,2*fp)] = lo;
        }
        p ^= 1;
        __syncthreads();
    }
}

extern "C" void kernel_launch(void* const* d_in, const int* in_sizes, int n_in,
                              void* d_out, int out_size)
{
    (void)in_sizes; (void)n_in; (void)out_size;
    prep<<<216, 256>>>((const float*)d_in[16], (const float*)d_in[17], (const float*)d_in[18],
                       (const float*)d_in[19], (const float*)d_in[20], (const float*)d_in[21],
                       (const float*)d_in[22]);
    cudaFuncSetAttribute(lstm_mma, cudaFuncAttributeMaxDynamicSharedMemorySize, SMEM_BYTES);
    lstm_mma<<<B_TOT/64, 256, SMEM_BYTES>>>(
        (const float*)d_in[8],  (const float*)d_in[9],  (const float*)d_in[10],
        (const float*)d_in[11], (const float*)d_in[12], (const float*)d_in[13],
        (const float*)d_in[14], (const float*)d_in[15],
        (const float*)d_in[23], (const float*)d_in[24], (float*)d_out);
}

// round 17
// speedup vs baseline: 2.0832x; 1.0676x over previous
#include <cuda_runtime.h>
#include <cuda_bf16.h>
#include <cstdint>
typedef unsigned u32; typedef unsigned long long u64; typedef uint16_t u16;

#define TS 30
#define WARM 24
#define B_TOT 8192

__device__ u32 gZh[36864], gZl[36864];
__device__ u32 g1h[9216], g1l[9216], g2h[9216], g2l[9216];

// ---------------- prep: weights -> bf16 hi/lo in B-fragment order (identical to R16) ----------------
__global__ void prep(const float* __restrict__ Wi, const float* __restrict__ Wh,
                     const float* __restrict__ bz, const float* __restrict__ W1,
                     const float* __restrict__ b1, const float* __restrict__ W2,
                     const float* __restrict__ b2){
    int idx = blockIdx.x*256 + threadIdx.x;
    const float *W=0, *bb=0; u32 *dh, *dl; int nts;
    if (idx < 36864){ nts=64; dh=gZh; dl=gZl; }
    else if (idx < 46080){ idx-=36864; nts=16; W=W1; bb=b1; dh=g1h; dl=g1l; }
    else if (idx < 55296){ idx-=46080; nts=16; W=W2; bb=b2; dh=g2h; dl=g2l; }
    else return;
    int fz = idx>>6, rem = idx&63, lane = rem>>1, reg = rem&1;
    int kt = fz/nts, ntg = fz%nts;
    int n = ntg*8 + (lane>>2);
    int k0 = kt*16 + 2*(lane&3) + reg*8;
    float v[2];
    #pragma unroll
    for (int e=0;e<2;e++){
        int k = k0+e; float x = 0.f;
        if (nts==64){
            int col = ((n&3)<<7) + (n>>2);
            if (k<128) x = Wh[k*512+col];
            else if (k<136) x = Wi[(k-128)*512+col];
            else if (k==136) x = bz[col];
        } else {
            if (k<128) x = W[k*128+n];
            else if (k==136) x = bb[n];
        }
        v[e] = x;
    }
    __nv_bfloat16 h0=__float2bfloat16(v[0]), h1=__float2bfloat16(v[1]);
    __nv_bfloat16 l0=__float2bfloat16(v[0]-__bfloat162float(h0));
    __nv_bfloat16 l1=__float2bfloat16(v[1]-__bfloat162float(h1));
    dh[fz*64+rem] = ((u32)(*(u16*)&h1)<<16) | (*(u16*)&h0);
    dl[fz*64+rem] = ((u32)(*(u16*)&l1)<<16) | (*(u16*)&l0);
}

__device__ __forceinline__ float sig_(float x){ return __fdividef(1.f, 1.f+__expf(-x)); }
__device__ __forceinline__ float th_(float x){ return 1.f - 2.f*__fdividef(1.f, __expf(2.f*x)+1.f); }
__device__ __forceinline__ void mma_(float* c, const u32* a, u32 b0, u32 b1){
    asm volatile("mma.sync.aligned.m16n8k16.row.col.f32.bf16.bf16.f32 "
        "{%0,%1,%2,%3},{%4,%5,%6,%7},{%8,%9},{%0,%1,%2,%3};"
        : "+f"(c[0]),"+f"(c[1]),"+f"(c[2]),"+f"(c[3])
        : "r"(a[0]),"r"(a[1]),"r"(a[2]),"r"(a[3]),"r"(b0),"r"(b1));
}
__device__ __forceinline__ void split2(float a, float b, u32& hi, u32& lo){
    __nv_bfloat16 ah=__float2bfloat16(a), bh=__float2bfloat16(b);
    __nv_bfloat16 al=__float2bfloat16(a-__bfloat162float(ah));
    __nv_bfloat16 bl=__float2bfloat16(b-__bfloat162float(bh));
    hi = ((u32)(*(u16*)&bh)<<16) | (*(u16*)&ah);
    lo = ((u32)(*(u16*)&bl)<<16) | (*(u16*)&al);
}
#define AIDX(kt,row,kpp) ((kt)*512 + (row)*8 + (kpp))
#define NT 512
#define SMEM_BYTES (27648*4 + (1024+64+128)*4)

__global__ void __launch_bounds__(NT,1)
lstm_mma(const float* __restrict__ x0, const float* __restrict__ x1, const float* __restrict__ x2,
         const float* __restrict__ x3, const float* __restrict__ x4, const float* __restrict__ x5,
         const float* __restrict__ x6, const float* __restrict__ irr,
         const float* __restrict__ Wout, const float* __restrict__ bout, float* __restrict__ out)
{
    extern __shared__ u32 sm[];
    u32* Mh = sm + 18432; u32* Ml = Mh + 4608;
    float* red   = (float*)(Ml + 4608);   // [16][64]
    float* predb = red + 1024;            // [64]
    float* woS   = predb + 64;            // [128]

    const int tid=threadIdx.x, lane=tid&31, w=tid>>5, g=lane>>2, l4=lane&3;
    const int b0 = blockIdx.x*64;

    for (int i=tid;i<27648;i+=NT) sm[i]=0;
    if (tid<128) woS[tid]=Wout[tid];
    const float boutv = bout[0];
    __syncthreads();
    if (tid<64){ // bias col 136 = 1.0 in Ah of both buffers + Mh (kt8, kpp1, byte0)
        u32 o = (AIDX(8,tid,1))*2;
        ((u16*)sm)[o] = 0x3F80;
        ((u16*)(sm+9216))[o] = 0x3F80;
        ((u16*)Mh)[o] = 0x3F80;
    }
    // features t=0 into buf0: f=tid>>6 (0..7), row=tid&63
    {
        int f=tid>>6, row=tid&63, gb=b0+row;
        const float* pf = (f==0)?x0:(f==1)?x1:(f==2)?x2:(f==3)?x3:(f==4)?x4:(f==5)?x5:(f==6)?x6:irr;
        float v = (f<7) ? __ldg(pf+gb*TS) : __ldg(pf+gb*WARM);
        __nv_bfloat16 hv=__float2bfloat16(v), lv=__float2bfloat16(v-__bfloat162float(hv));
        u32 o = (AIDX(8,row,(f>>1)*2))*2 + (f&1);
        ((u16*)sm)[o] = *(u16*)&hv;
        ((u16*)(sm+4608))[o] = *(u16*)&lv;
    }
    float cst[32];
    #pragma unroll
    for (int i=0;i<32;i++) cst[i]=0.f;
    int p = 0;
    __syncthreads();

    for (int t=0; t<TS; t++){
        const u32* Ah = sm + p*9216; const u32* Al = Ah + 4608;
        u32* NAh = sm + (p^1)*9216;  u32* NAl = NAh + 4608;

        // ============ z GEMM (2 halves x 2 ntg) + gates ============
        #pragma unroll
        for (int hf=0; hf<2; hf++){
            float acc[2][4][4];
            #pragma unroll
            for (int a_=0;a_<2;a_++)
                #pragma unroll
                for (int b_=0;b_<4;b_++){ acc[a_][b_][0]=0;acc[a_][b_][1]=0;acc[a_][b_][2]=0;acc[a_][b_][3]=0; }
            for (int kt=0; kt<9; kt++){
                u32 ah[4][4], al[4][4];
                #pragma unroll
                for (int mt=0;mt<4;mt++){
                    int base = AIDX(kt, mt*16+g, 2*l4);
                    u64 va = *(const u64*)(Ah+base), vb = *(const u64*)(Ah+base+64);
                    ah[mt][0]=(u32)va; ah[mt][2]=(u32)(va>>32);
                    ah[mt][1]=(u32)vb; ah[mt][3]=(u32)(vb>>32);
                    u64 vc = *(const u64*)(Al+base), vd = *(const u64*)(Al+base+64);
                    al[mt][0]=(u32)vc; al[mt][2]=(u32)(vc>>32);
                    al[mt][1]=(u32)vd; al[mt][3]=(u32)(vd>>32);
                }
                #pragma unroll
                for (int nt=0;nt<2;nt++){
                    int ntg = w*4 + hf*2 + nt;
                    u64 vh = ((const u64*)gZh)[(kt*64+ntg)*32 + lane];
                    u64 vl = ((const u64*)gZl)[(kt*64+ntg)*32 + lane];
                    #pragma unroll
                    for (int mt=0;mt<4;mt++){
                        mma_(acc[nt][mt], ah[mt], (u32)vh, (u32)(vh>>32));
                        mma_(acc[nt][mt], al[mt], (u32)vh, (u32)(vh>>32));
                        mma_(acc[nt][mt], ah[mt], (u32)vl, (u32)(vl>>32));
                    }
                }
            }
            // gates
            #pragma unroll
            for (int nt=0;nt<2;nt++){
                int ntg = w*4 + hf*2 + nt;
                int ch  = ntg*2 + (l4>>1);
                int kth = ch>>4, kpi = ntg&7;
                int kpp = (kpi&3)*2 + (kpi>>2);
                int byte_ = l4>>1;
                #pragma unroll
                for (int mt=0;mt<4;mt++){
                    float* c = acc[nt][mt];
                    float t0=__shfl_xor_sync(0xffffffffu,c[0],1);
                    float t1=__shfl_xor_sync(0xffffffffu,c[1],1);
                    float t2=__shfl_xor_sync(0xffffffffu,c[2],1);
                    float t3=__shfl_xor_sync(0xffffffffu,c[3],1);
                    bool odd = (l4&1);
                    float zi0=odd?t0:c[0], zf0=odd?t1:c[1], zg0=odd?c[0]:t0, zo0=odd?c[1]:t1;
                    float zi1=odd?t2:c[2], zf1=odd?t3:c[3], zg1=odd?c[2]:t2, zo1=odd?c[3]:t3;
                    int ci = ((hf*2+nt)*4+mt)*2;
                    float cc0 = sig_(zf0)*cst[ci]   + sig_(zi0)*th_(zg0);
                    float cc1 = sig_(zf1)*cst[ci+1] + sig_(zi1)*th_(zg1);
                    cst[ci]=cc0; cst[ci+1]=cc1;
                    float h0 = sig_(zo0)*th_(cc0), h1 = sig_(zo1)*th_(cc1);
                    int row = mt*16+g;
                    u16* dst = odd ? (u16*)NAl : (u16*)NAh;
                    __nv_bfloat16 e0=__float2bfloat16(h0), e1=__float2bfloat16(h1);
                    if (odd){ e0=__float2bfloat16(h0-__bfloat162float(__float2bfloat16(h0)));
                              e1=__float2bfloat16(h1-__bfloat162float(__float2bfloat16(h1))); }
                    dst[(AIDX(kth,row,  kpp))*2 + byte_] = *(u16*)&e0;
                    dst[(AIDX(kth,row+8,kpp))*2 + byte_] = *(u16*)&e1;
                }
            }
        }
        __syncthreads();

        // ============ m1 = relu(h@W1+b1): 1 ntg per warp ============
        {
            float acc[4][4];
            #pragma unroll
            for (int b_=0;b_<4;b_++){ acc[b_][0]=0;acc[b_][1]=0;acc[b_][2]=0;acc[b_][3]=0; }
            for (int kt=0; kt<9; kt++){
                u32 ah[4][4], al[4][4];
                #pragma unroll
                for (int mt=0;mt<4;mt++){
                    int base = AIDX(kt, mt*16+g, 2*l4);
                    u64 va = *(const u64*)(NAh+base), vb = *(const u64*)(NAh+base+64);
                    ah[mt][0]=(u32)va; ah[mt][2]=(u32)(va>>32);
                    ah[mt][1]=(u32)vb; ah[mt][3]=(u32)(vb>>32);
                    u64 vc = *(const u64*)(NAl+base), vd = *(const u64*)(NAl+base+64);
                    al[mt][0]=(u32)vc; al[mt][2]=(u32)(vc>>32);
                    al[mt][1]=(u32)vd; al[mt][3]=(u32)(vd>>32);
                }
                u64 vh = ((const u64*)g1h)[(kt*16+w)*32 + lane];
                u64 vl = ((const u64*)g1l)[(kt*16+w)*32 + lane];
                #pragma unroll
                for (int mt=0;mt<4;mt++){
                    mma_(acc[mt], ah[mt], (u32)vh, (u32)(vh>>32));
                    mma_(acc[mt], al[mt], (u32)vh, (u32)(vh>>32));
                    mma_(acc[mt], ah[mt], (u32)vl, (u32)(vl>>32));
                }
            }
            int ktM = w>>1, kppM = l4*2 + (w&1);
            #pragma unroll
            for (int mt=0;mt<4;mt++){
                float* c = acc[mt];
                int row = mt*16+g;
                u32 hi,lo;
                split2(fmaxf(c[0],0.f), fmaxf(c[1],0.f), hi, lo);
                Mh[AIDX(ktM,row,kppM)] = hi; Ml[AIDX(ktM,row,kppM)] = lo;
                split2(fmaxf(c[2],0.f), fmaxf(c[3],0.f), hi, lo);
                Mh[AIDX(ktM,row+8,kppM)] = hi; Ml[AIDX(ktM,row+8,kppM)] = lo;
            }
        }
        __syncthreads();

        // ============ m2 + out-projection ============
        {
            float acc[4][4];
            #pragma unroll
            for (int b_=0;b_<4;b_++){ acc[b_][0]=0;acc[b_][1]=0;acc[b_][2]=0;acc[b_][3]=0; }
            for (int kt=0; kt<9; kt++){
                u32 ah[4][4], al[4][4];
                #pragma unroll
                for (int mt=0;mt<4;mt++){
                    int base = AIDX(kt, mt*16+g, 2*l4);
                    u64 va = *(const u64*)(Mh+base), vb = *(const u64*)(Mh+base+64);
                    ah[mt][0]=(u32)va; ah[mt][2]=(u32)(va>>32);
                    ah[mt][1]=(u32)vb; ah[mt][3]=(u32)(vb>>32);
                    u64 vc = *(const u64*)(Ml+base), vd = *(const u64*)(Ml+base+64);
                    al[mt][0]=(u32)vc; al[mt][2]=(u32)(vc>>32);
                    al[mt][1]=(u32)vd; al[mt][3]=(u32)(vd>>32);
                }
                u64 vh = ((const u64*)g2h)[(kt*16+w)*32 + lane];
                u64 vl = ((const u64*)g2l)[(kt*16+w)*32 + lane];
                #pragma unroll
                for (int mt=0;mt<4;mt++){
                    mma_(acc[mt], ah[mt], (u32)vh, (u32)(vh>>32));
                    mma_(acc[mt], al[mt], (u32)vh, (u32)(vh>>32));
                    mma_(acc[mt], ah[mt], (u32)vl, (u32)(vl>>32));
                }
            }
            int n = w*8 + 2*l4;
            #pragma unroll
            for (int mt=0;mt<4;mt++){
                float* c = acc[mt];
                float p0 = fmaxf(c[0],0.f)*woS[n] + fmaxf(c[1],0.f)*woS[n+1];
                float p1 = fmaxf(c[2],0.f)*woS[n] + fmaxf(c[3],0.f)*woS[n+1];
                p0 += __shfl_xor_sync(0xffffffffu,p0,1); p0 += __shfl_xor_sync(0xffffffffu,p0,2);
                p1 += __shfl_xor_sync(0xffffffffu,p1,1); p1 += __shfl_xor_sync(0xffffffffu,p1,2);
                if (l4==0){ red[w*64 + mt*16+g] = p0; red[w*64 + mt*16+g+8] = p1; }
            }
        }
        __syncthreads();
        if (tid < 64){
            float s = boutv;
            #pragma unroll
            for (int j=0;j<16;j++) s += red[j*64+tid];
            predb[tid] = s;
            out[(size_t)(b0+tid)*TS + t] = s;
        }
        __syncthreads();
        // features t+1 -> NA buffer
        if (t+1 < TS){
            int f=tid>>6, row=tid&63, gb=b0+row;
            const float* pf = (f==0)?x0:(f==1)?x1:(f==2)?x2:(f==3)?x3:(f==4)?x4:(f==5)?x5:(f==6)?x6:irr;
            float v;
            if (f<7) v = __ldg(pf + gb*TS + t+1);
            else v = (t+1<WARM) ? __ldg(pf + gb*WARM + t+1) : predb[row];
            __nv_bfloat16 hv=__float2bfloat16(v), lv=__float2bfloat16(v-__bfloat162float(hv));
            u32 o = (AIDX(8,row,(f>>1)*2))*2 + (f&1);
            ((u16*)NAh)[o] = *(u16*)&hv;
            ((u16*)NAl)[o] = *(u16*)&lv;
        }
        p ^= 1;
        __syncthreads();
    }
}

extern "C" void kernel_launch(void* const* d_in, const int* in_sizes, int n_in,
                              void* d_out, int out_size)
{
    (void)in_sizes; (void)n_in; (void)out_size;
    prep<<<216, 256>>>((const float*)d_in[16], (const float*)d_in[17], (const float*)d_in[18],
                       (const float*)d_in[19], (const float*)d_in[20], (const float*)d_in[21],
                       (const float*)d_in[22]);
    cudaFuncSetAttribute(lstm_mma, cudaFuncAttributeMaxDynamicSharedMemorySize, SMEM_BYTES);
    lstm_mma<<<B_TOT/64, NT, SMEM_BYTES>>>(
        (const float*)d_in[8],  (const float*)d_in[9],  (const float*)d_in[10],
        (const float*)d_in[11], (const float*)d_in[12], (const float*)d_in[13],
        (const float*)d_in[14], (const float*)d_in[15],
        (const float*)d_in[23], (const float*)d_in[24], (float*)d_out);
}